// round 9
// baseline (speedup 1.0000x reference)
#include <cuda_runtime.h>

// inputs (128, 64, 64, 32) fp32 => B=128, N=64 rows/batch, D=2048.
// loss = mean_b( || sum_n att[b,n,:] ||^2 - sum_n <att_n,att_n> ),
// att = x / max(||x||,1e-12) row-wise.
//
// SINGLE-PASS kernel: each element read once. Block (b,h) owns rows
// [32h,32h+32) of batch b. Per iteration: 512-thread group loads one full
// row into registers, block-reduces sumsq -> inv, then FMAs inv*x into
// per-thread column accumulators. Two groups (even/odd rows) share one
// barrier per iteration via double-buffered scratch.

#define BB   128
#define NN   64
#define DD   2048
#define NF4  (DD / 4)     // 512 float4 columns
#define NT   1024
#define GRID (BB * 2)     // 256 blocks, 2 per batch

__device__ float4       g_s[BB][2][NF4];   // per-(batch,half) partial col sums
__device__ float        g_diagp[GRID];     // per-block diag partial
__device__ double       g_part[BB];        // per-batch t1 - t2
__device__ unsigned int g_pair[BB];        // monotonic (never reset)
__device__ unsigned int g_done;            // monotonic (never reset)

__global__ __launch_bounds__(NT, 2) void fused_loss(const float* __restrict__ x,
                                                    float* __restrict__ out) {
    const int bid  = blockIdx.x;
    const int b    = bid >> 1;
    const int h    = bid & 1;
    const int t    = threadIdx.x;
    const int warp = t >> 5;
    const int lane = t & 31;
    const int col  = t & (NF4 - 1);   // 0..511
    const int par  = t >> 9;          // 0: even rows, 1: odd rows

    __shared__ float  ws[2][32];      // double-buffered cross-warp scratch
    __shared__ float4 sbuf[NF4];      // half-combine exchange (8 KB)
    __shared__ float  sdiag;
    __shared__ bool   s_second, s_last;
    __shared__ double sdd[BB];

    // rows handled by this thread: h*32 + 2*it + par, it = 0..15
    const float4* p = reinterpret_cast<const float4*>(x + (size_t)b * NN * DD)
                      + (size_t)(h * 32 + par) * NF4 + col;

    float4 s    = make_float4(0.f, 0.f, 0.f, 0.f);
    float  diag = 0.f;
    float4 a    = p[0];                       // prefetch row (it=0)

    #pragma unroll 1
    for (int it = 0; it < 16; it++) {
        const float4 cur = a;
        if (it < 15) a = p[(2 * (it + 1)) * NF4];   // prefetch next row

        // row sum-of-squares: 512-thread group reduction
        float part = cur.x*cur.x + cur.y*cur.y + cur.z*cur.z + cur.w*cur.w;
        #pragma unroll
        for (int o = 16; o; o >>= 1) part += __shfl_xor_sync(0xffffffffu, part, o);
        if (lane == 0) ws[it & 1][warp] = part;
        __syncthreads();

        float ss = 0.f;
        const float* wv = ws[it & 1] + (par << 4);  // this group's 16 warps
        #pragma unroll
        for (int j = 0; j < 16; j++) ss += wv[j];

        // inv = 1/max(||row||,1e-12); guard keeps rsqrtf finite
        const float inv = rsqrtf(fmaxf(ss, 1e-24f));
        if (col == 0) diag += ss * inv * inv;       // one thread per group

        s.x = fmaf(inv, cur.x, s.x); s.y = fmaf(inv, cur.y, s.y);
        s.z = fmaf(inv, cur.z, s.z); s.w = fmaf(inv, cur.w, s.w);
    }

    // combine even/odd groups -> this block's 32-row partial column sums
    if (par == 1) {
        sbuf[col] = s;
        if (col == 0) sdiag = diag;
    }
    __syncthreads();
    if (par == 0) {
        const float4 q = sbuf[col];
        s.x += q.x; s.y += q.y; s.z += q.z; s.w += q.w;
        g_s[b][h][col] = s;                    // 8 KB partial to global
    }
    if (t == 0) g_diagp[bid] = diag + sdiag;
    __syncthreads();                           // all STG issued before fence

    // ---- pair sync: second-arriving block of (b) computes t1_b ------------
    if (t == 0) {
        __threadfence();
        unsigned int old = atomicAdd(&g_pair[b], 1u);
        s_second = ((old & 1u) == 1u);
    }
    __syncthreads();
    if (!s_second) return;
    __threadfence();

    float v1 = 0.f;
    if (t < NF4) {
        const float4 A = g_s[b][0][t];
        const float4 C = g_s[b][1][t];
        const float sx = A.x + C.x, sy = A.y + C.y;
        const float sz = A.z + C.z, sw = A.w + C.w;
        v1 = sx*sx + sy*sy + sz*sz + sw*sw;
    }
    #pragma unroll
    for (int o = 16; o; o >>= 1) v1 += __shfl_xor_sync(0xffffffffu, v1, o);
    if (lane == 0) ws[0][warp] = v1;
    __syncthreads();

    if (t == 0) {
        float t1 = 0.f;
        #pragma unroll
        for (int i = 0; i < 32; i++) t1 += ws[0][i];
        const double t2 = (double)g_diagp[2 * b] + (double)g_diagp[2 * b + 1];
        g_part[b] = (double)t1 - t2;
        __threadfence();
        unsigned int old = atomicAdd(&g_done, 1u);
        s_last = ((old & (unsigned int)(BB - 1)) == (unsigned int)(BB - 1));
    }
    __syncthreads();
    if (!s_last) return;

    // ---- global finisher: combine 128 per-batch doubles -------------------
    __threadfence();
    if (t < BB) sdd[t] = g_part[t];
    __syncthreads();
    #pragma unroll
    for (int o = BB / 2; o; o >>= 1) {
        if (t < o) sdd[t] += sdd[t + o];
        __syncthreads();
    }
    if (t == 0) out[0] = (float)(sdd[0] / (double)BB);
}

extern "C" void kernel_launch(void* const* d_in, const int* in_sizes, int n_in,
                              void* d_out, int out_size) {
    (void)in_sizes; (void)n_in; (void)out_size;
    const float* x = (const float*)d_in[0];
    float* out = (float*)d_out;
    fused_loss<<<GRID, NT>>>(x, out);
}

// round 10
// speedup vs baseline: 1.4552x; 1.4552x over previous
#include <cuda_runtime.h>

// inputs (128, 64, 64, 32) fp32 => B=128, N=64 rows/batch, D=2048.
// loss = mean_b( || sum_n att[b,n,:] ||^2 - sum_n <att_n,att_n> ),
// att = x / max(||x||,1e-12) row-wise.
//
// SINGLE-PASS: each element read exactly once. Block (b,h) owns rows
// [32h,32h+32). 512 threads = 4 groups x 128; group g sweeps rows
// g*8..g*8+7; each thread holds 4 float4 columns of the row. Row norm:
// warp shuffle + 4-value smem combine; then FMA inv*x into per-thread
// column accumulators. One block barrier per iteration (double-buffered).

#define BB   128
#define NN   64
#define DD   2048
#define NF4  (DD / 4)       // 512 f4 columns
#define NT   512
#define NG   4              // groups per block
#define GT   128            // threads per group
#define RPG  8              // rows per group
#define GRID (BB * 2)

__device__ float4       g_s[BB][2][NF4];  // per-(batch,half) partial col sums
__device__ float        g_diagp[GRID];
__device__ double       g_part[BB];
__device__ unsigned int g_pair[BB];       // monotonic
__device__ unsigned int g_done;           // monotonic

__global__ __launch_bounds__(NT, 2) void fused_loss(const float* __restrict__ x,
                                                    float* __restrict__ out) {
    const int bid  = blockIdx.x;
    const int b    = bid >> 1;
    const int h    = bid & 1;
    const int t    = threadIdx.x;
    const int g    = t >> 7;          // group 0..3
    const int gt   = t & (GT - 1);    // 0..127 within group
    const int gw   = gt >> 5;         // warp within group 0..3
    const int lane = t & 31;

    __shared__ float  ws[2][NG][4];       // double-buffered row partials
    __shared__ float4 sbuf[NG - 1][GT][4];// group-combine (24 KB)
    __shared__ float  sdiag[NG];
    __shared__ float  w1[NT / 32];
    __shared__ bool   s_second, s_last;
    __shared__ double sdd[BB];

    const float4* base4 = reinterpret_cast<const float4*>(x + (size_t)b * NN * DD);
    const int row0 = h * 32 + g * RPG;

    float4 s[4];
    #pragma unroll
    for (int j = 0; j < 4; j++) s[j] = make_float4(0.f, 0.f, 0.f, 0.f);
    float diag = 0.f;

    float4 cur[4];
    {
        const float4* p = base4 + (size_t)row0 * NF4 + gt;
        #pragma unroll
        for (int j = 0; j < 4; j++) cur[j] = p[j * GT];
    }

    #pragma unroll 1
    for (int it = 0; it < RPG; it++) {
        float4 nxt[4];
        if (it < RPG - 1) {
            const float4* p = base4 + (size_t)(row0 + it + 1) * NF4 + gt;
            #pragma unroll
            for (int j = 0; j < 4; j++) nxt[j] = p[j * GT];
        }

        // per-thread sumsq over 16 elements
        float ss = 0.f;
        #pragma unroll
        for (int j = 0; j < 4; j++) {
            ss = fmaf(cur[j].x, cur[j].x, ss);
            ss = fmaf(cur[j].y, cur[j].y, ss);
            ss = fmaf(cur[j].z, cur[j].z, ss);
            ss = fmaf(cur[j].w, cur[j].w, ss);
        }
        #pragma unroll
        for (int o = 16; o; o >>= 1) ss += __shfl_xor_sync(0xffffffffu, ss, o);
        if (lane == 0) ws[it & 1][g][gw] = ss;
        __syncthreads();

        const float* wv = ws[it & 1][g];
        const float rs = (wv[0] + wv[1]) + (wv[2] + wv[3]);
        const float inv = rsqrtf(fmaxf(rs, 1e-24f));   // 1/max(||row||,eps)
        if (gt == 0) diag += rs * inv * inv;

        #pragma unroll
        for (int j = 0; j < 4; j++) {
            s[j].x = fmaf(inv, cur[j].x, s[j].x);
            s[j].y = fmaf(inv, cur[j].y, s[j].y);
            s[j].z = fmaf(inv, cur[j].z, s[j].z);
            s[j].w = fmaf(inv, cur[j].w, s[j].w);
        }
        #pragma unroll
        for (int j = 0; j < 4; j++) cur[j] = nxt[j];
    }

    // combine the 4 groups' column partials (same columns, different rows)
    if (g > 0) {
        #pragma unroll
        for (int j = 0; j < 4; j++) sbuf[g - 1][gt][j] = s[j];
        if (gt == 0) sdiag[g] = diag;
    }
    __syncthreads();
    if (g == 0) {
        #pragma unroll
        for (int j = 0; j < 4; j++) {
            #pragma unroll
            for (int k = 0; k < NG - 1; k++) {
                const float4 q = sbuf[k][gt][j];
                s[j].x += q.x; s[j].y += q.y; s[j].z += q.z; s[j].w += q.w;
            }
            g_s[b][h][gt + j * GT] = s[j];
        }
    }
    if (t == 0) g_diagp[bid] = diag + sdiag[1] + sdiag[2] + sdiag[3];
    __syncthreads();

    // ---- pair sync (non-blocking): second arrival combines the batch ------
    if (t == 0) {
        __threadfence();
        unsigned int old = atomicAdd(&g_pair[b], 1u);
        s_second = ((old & 1u) == 1u);
    }
    __syncthreads();
    if (!s_second) return;
    __threadfence();

    float v1 = 0.f;
    {   // 512 threads, one f4 column each
        const float4 A = g_s[b][0][t];
        const float4 C = g_s[b][1][t];
        const float sx = A.x + C.x, sy = A.y + C.y;
        const float sz = A.z + C.z, sw = A.w + C.w;
        v1 = sx * sx + sy * sy + sz * sz + sw * sw;
    }
    #pragma unroll
    for (int o = 16; o; o >>= 1) v1 += __shfl_xor_sync(0xffffffffu, v1, o);
    if (lane == 0) w1[t >> 5] = v1;
    __syncthreads();

    if (t == 0) {
        float t1 = 0.f;
        #pragma unroll
        for (int i = 0; i < NT / 32; i++) t1 += w1[i];
        const double t2 = (double)g_diagp[2 * b] + (double)g_diagp[2 * b + 1];
        g_part[b] = (double)t1 - t2;
        __threadfence();
        unsigned int old = atomicAdd(&g_done, 1u);
        s_last = ((old & (unsigned int)(BB - 1)) == (unsigned int)(BB - 1));
    }
    __syncthreads();
    if (!s_last) return;

    // ---- finisher: combine 128 per-batch doubles --------------------------
    __threadfence();
    if (t < BB) sdd[t] = g_part[t];
    __syncthreads();
    #pragma unroll
    for (int o = BB / 2; o; o >>= 1) {
        if (t < o) sdd[t] += sdd[t + o];
        __syncthreads();
    }
    if (t == 0) out[0] = (float)(sdd[0] / (double)BB);
}

extern "C" void kernel_launch(void* const* d_in, const int* in_sizes, int n_in,
                              void* d_out, int out_size) {
    (void)in_sizes; (void)n_in; (void)out_size;
    const float* x = (const float*)d_in[0];
    float* out = (float*)d_out;
    fused_loss<<<GRID, NT>>>(x, out);
}